// round 14
// baseline (speedup 1.0000x reference)
#include <cuda_runtime.h>
#include <math.h>
#include <stdint.h>

// ---------------------------------------------------------------------------
// Model dims
// ---------------------------------------------------------------------------
#define NP   4096
#define BB   4
#define TT   1024
#define DM   1024
#define HH   16
#define HS   64
#define DFF  4096
#define LL   6
#define VV   32000
#define DBK  64
#define DIN  1088
#define QKVN 3072
#define ZZ   (BB * HH)          /* 64 (b,h) pairs */

// Weight arena offsets (elements)
#define OFF_QKV 0ull
#define OFF_WO  18874368ull
#define OFF_W1  25165824ull
#define OFF_W2  51904512ull
#define OFF_WH  77070336ull
#define WT_TOTAL 109838336ull

// Fused transpose tile counts (64x64 tiles)
#define TIL_SQ   256
#define TIL_W1   1088
#define TIL_W2   1024
#define TIL_LAYER (4 * TIL_SQ + TIL_W1 + TIL_W2)
#define TIL_WH   8000
#define TIL_TOTAL (LL * TIL_LAYER + TIL_WH)

// ---------------------------------------------------------------------------
// Scratch
// ---------------------------------------------------------------------------
__device__ __align__(128) float g_x  [NP * DM];
__device__ __align__(128) float g_h  [NP * DM];
__device__ __align__(128) float g_qkv[NP * QKVN];
__device__ __align__(128) float g_ao [NP * DM];
__device__ __align__(128) float g_h2 [NP * DIN];
__device__ __align__(128) float g_ff [NP * DFF];
__device__ __align__(128) float g_wt [WT_TOTAL];
__device__ __align__(128) float g_s  [(size_t)ZZ * TT * TT];   // attention scores
__device__ __align__(128) float g_vt [(size_t)ZZ * HS * TT];   // V^T per (b,h)
__device__ float g_rowloss[NP];

// ---------------------------------------------------------------------------
// Helpers
// ---------------------------------------------------------------------------
__device__ __forceinline__ uint32_t smem_u32(const void* p) {
    uint32_t a;
    asm("{ .reg .u64 t; cvta.to.shared.u64 t, %1; cvt.u32.u64 %0, t; }"
        : "=r"(a) : "l"(p));
    return a;
}

__device__ __forceinline__ float rtf32(float x) {
    uint32_t u;
    asm("cvt.rna.tf32.f32 %0, %1;" : "=r"(u) : "f"(x));
    return __uint_as_float(u);
}

__device__ __forceinline__ void cp16(uint32_t dst, const void* src) {
    asm volatile("cp.async.cg.shared.global [%0], [%1], 16;" ::"r"(dst), "l"(src));
}

#define LDSM4(r, a)                                                            \
    asm volatile("ldmatrix.sync.aligned.m8n8.x4.shared.b16 {%0,%1,%2,%3}, [%4];" \
                 : "=r"((r)[0]), "=r"((r)[1]), "=r"((r)[2]), "=r"((r)[3])      \
                 : "r"(a))

#define MMA_TF32(d, a, b)                                                      \
    asm volatile(                                                              \
        "mma.sync.aligned.m16n8k8.row.col.f32.tf32.tf32.f32 "                  \
        "{%0,%1,%2,%3}, {%4,%5,%6,%7}, {%8,%9}, {%0,%1,%2,%3};\n"              \
        : "+f"(d[0]), "+f"(d[1]), "+f"(d[2]), "+f"(d[3])                       \
        : "r"(a[0]), "r"(a[1]), "r"(a[2]), "r"(a[3]), "r"(b[0]), "r"(b[1]))

__device__ __forceinline__ float warpSum(float v) {
#pragma unroll
    for (int o = 16; o; o >>= 1) v += __shfl_xor_sync(0xffffffffu, v, o);
    return v;
}
__device__ __forceinline__ float warpMax(float v) {
#pragma unroll
    for (int o = 16; o; o >>= 1) v = fmaxf(v, __shfl_xor_sync(0xffffffffu, v, o));
    return v;
}

__device__ __forceinline__ float blockReduceSum(float v) {
    __shared__ float sm[33];
    int lane = threadIdx.x & 31, w = threadIdx.x >> 5;
    v = warpSum(v);
    if (lane == 0) sm[w] = v;
    __syncthreads();
    if (w == 0) {
        v = (lane < (blockDim.x >> 5)) ? sm[lane] : 0.f;
        v = warpSum(v);
        if (lane == 0) sm[32] = v;
    }
    __syncthreads();
    return sm[32];
}
__device__ __forceinline__ float blockReduceMax(float v) {
    __shared__ float sm[33];
    int lane = threadIdx.x & 31, w = threadIdx.x >> 5;
    v = warpMax(v);
    if (lane == 0) sm[w] = v;
    __syncthreads();
    if (w == 0) {
        v = (lane < (blockDim.x >> 5)) ? sm[lane] : -1e30f;
        v = warpMax(v);
        if (lane == 0) sm[32] = v;
    }
    __syncthreads();
    return sm[32];
}

// ---------------------------------------------------------------------------
// Elementwise kernels
// ---------------------------------------------------------------------------
__global__ void embed_kernel(const int* __restrict__ idx,
                             const float* __restrict__ tok,
                             const float* __restrict__ pos) {
    int gid = blockIdx.x * 256 + threadIdx.x;
    int n = gid >> 8, c4 = (gid & 255) * 4;
    int t = n & (TT - 1);
    const float4 a = *(const float4*)(tok + (size_t)idx[n] * DM + c4);
    const float4 b = *(const float4*)(pos + (size_t)t * DM + c4);
    float4 o;
    o.x = a.x + b.x; o.y = a.y + b.y; o.z = a.z + b.z; o.w = a.w + b.w;
    *(float4*)(g_x + (size_t)n * DM + c4) = o;
}

__global__ void book_kernel(const int* __restrict__ ibx,
                            const float* __restrict__ book) {
    int gid = blockIdx.x * 256 + threadIdx.x;
    int n = gid >> 6, d = gid & 63, b = n >> 10;
    g_h2[(size_t)n * DIN + DM + d] = rtf32(book[ibx[b] * DBK + d]);
}

// LayerNorm: warp per row, 8 rows/block (256 threads).
__global__ __launch_bounds__(256) void ln_kernel(
    const float* __restrict__ x, const float* __restrict__ sc,
    const float* __restrict__ bi, float* __restrict__ y, int ldo) {
    int warp = threadIdx.x >> 5, lane = threadIdx.x & 31;
    int row = blockIdx.x * 8 + warp;
    const float4* xr = (const float4*)(x + (size_t)row * DM);
    float4 v[8];
    float sum = 0.f;
#pragma unroll
    for (int i = 0; i < 8; i++) {
        v[i] = xr[i * 32 + lane];
        sum += v[i].x + v[i].y + v[i].z + v[i].w;
    }
    float mu = warpSum(sum) * (1.f / DM);
    float sq = 0.f;
#pragma unroll
    for (int i = 0; i < 8; i++) {
        float dx = v[i].x - mu, dy = v[i].y - mu;
        float dz = v[i].z - mu, dw = v[i].w - mu;
        sq += dx * dx + dy * dy + dz * dz + dw * dw;
    }
    float rstd = rsqrtf(warpSum(sq) * (1.f / DM) + 1e-5f);
#pragma unroll
    for (int i = 0; i < 8; i++) {
        int c4 = i * 32 + lane;
        float4 s4 = ((const float4*)sc)[c4];
        float4 b4 = ((const float4*)bi)[c4];
        float4 o;
        o.x = rtf32((v[i].x - mu) * rstd * s4.x + b4.x);
        o.y = rtf32((v[i].y - mu) * rstd * s4.y + b4.y);
        o.z = rtf32((v[i].z - mu) * rstd * s4.z + b4.z);
        o.w = rtf32((v[i].w - mu) * rstd * s4.w + b4.w);
        *(float4*)(y + (size_t)row * ldo + c4 * 4) = o;
    }
}

// ---------------------------------------------------------------------------
// Fused weight transpose + tf32 round (one launch for all weights)
// ---------------------------------------------------------------------------
__device__ __forceinline__ void wtr_tile(const float* __restrict__ W,
                                         float* __restrict__ Wt, int K, int N,
                                         int tile) {
    __shared__ float s[64][65];
    int tiles_n = N >> 6;
    int n0 = (tile % tiles_n) << 6;
    int k0 = (tile / tiles_n) << 6;
    int t = threadIdx.x;
    int kk = t >> 4, nn4 = (t & 15) * 4;
#pragma unroll
    for (int i = 0; i < 4; i++) {
        int k = kk + 16 * i;
        float4 w = *(const float4*)(W + (size_t)(k0 + k) * N + n0 + nn4);
        s[nn4 + 0][k] = w.x;
        s[nn4 + 1][k] = w.y;
        s[nn4 + 2][k] = w.z;
        s[nn4 + 3][k] = w.w;
    }
    __syncthreads();
    int k4 = (t & 15) * 4;
#pragma unroll
    for (int i = 0; i < 4; i++) {
        int n = (t >> 4) + 16 * i;
        float4 o;
        o.x = rtf32(s[n][k4 + 0]);
        o.y = rtf32(s[n][k4 + 1]);
        o.z = rtf32(s[n][k4 + 2]);
        o.w = rtf32(s[n][k4 + 3]);
        *(float4*)(Wt + (size_t)(n0 + n) * K + k0 + k4) = o;
    }
}

__global__ __launch_bounds__(256) void wtr_all_kernel(
    const float* __restrict__ Wq, const float* __restrict__ Wk,
    const float* __restrict__ Wv, const float* __restrict__ Wo,
    const float* __restrict__ W1, const float* __restrict__ W2,
    const float* __restrict__ Wh, float* __restrict__ wt) {
    int b = blockIdx.x;
    if (b < LL * TIL_LAYER) {
        int l = b / TIL_LAYER, r = b % TIL_LAYER;
        if (r < 4 * TIL_SQ) {
            int w = r >> 8, tile = r & 255;
            const float* src;
            float* dst;
            size_t lofs = (size_t)l * DM * DM;
            if (w == 0) {
                src = Wq + lofs;
                dst = wt + OFF_QKV + (size_t)l * 3 * DM * DM;
            } else if (w == 1) {
                src = Wk + lofs;
                dst = wt + OFF_QKV + (size_t)l * 3 * DM * DM + (size_t)DM * DM;
            } else if (w == 2) {
                src = Wv + lofs;
                dst = wt + OFF_QKV + (size_t)l * 3 * DM * DM + 2ull * DM * DM;
            } else {
                src = Wo + lofs;
                dst = wt + OFF_WO + lofs;
            }
            wtr_tile(src, dst, DM, DM, tile);
        } else if (r < 4 * TIL_SQ + TIL_W1) {
            wtr_tile(W1 + (size_t)l * DIN * DFF, wt + OFF_W1 + (size_t)l * DFF * DIN,
                     DIN, DFF, r - 4 * TIL_SQ);
        } else {
            wtr_tile(W2 + (size_t)l * DFF * DM, wt + OFF_W2 + (size_t)l * DM * DFF,
                     DFF, DM, r - 4 * TIL_SQ - TIL_W1);
        }
    } else {
        wtr_tile(Wh, wt + OFF_WH, DM, VV, b - LL * TIL_LAYER);
    }
}

// V^T: qkv V-part -> g_vt[z][d][j]  (z = b*16+h)
__global__ __launch_bounds__(256) void vt_kernel() {
    __shared__ float s[64][65];
    int z = blockIdx.y, jt = blockIdx.x;
    int b = z >> 4, h = z & 15;
    int t = threadIdx.x;
    int rr = t >> 4, c4 = (t & 15) * 4;
#pragma unroll
    for (int i = 0; i < 4; i++) {
        int r = rr + 16 * i;
        const float4 w = *(const float4*)(g_qkv +
            (size_t)(b * TT + jt * 64 + r) * QKVN + 2048 + h * 64 + c4);
        s[c4 + 0][r] = w.x;
        s[c4 + 1][r] = w.y;
        s[c4 + 2][r] = w.z;
        s[c4 + 3][r] = w.w;
    }
    __syncthreads();
#pragma unroll
    for (int i = 0; i < 4; i++) {
        int d = rr + 16 * i;
        float4 o;
        o.x = s[d][c4 + 0];
        o.y = s[d][c4 + 1];
        o.z = s[d][c4 + 2];
        o.w = s[d][c4 + 3];
        *(float4*)(g_vt + (size_t)z * (HS * TT) + (size_t)d * TT + jt * 64 + c4) = o;
    }
}

// ---------------------------------------------------------------------------
// hgemm3: linear-layer tf32 GEMM. 128x128 CTA tile, 128 threads (4 warps,
// warp tile 64x64), BK=32, 3-stage cp.async, 2 CTA/SM.
// ---------------------------------------------------------------------------
#define STG3 32768
#define GEMM3_SMEM (3 * STG3)

__global__ __launch_bounds__(128, 2) void hgemm3(
    const float* __restrict__ A, int lda,
    const float* __restrict__ Bt, int ldb,
    const float* __restrict__ bias, const float* __restrict__ res,
    float* __restrict__ C, int M, int N, int K, int relu, int rnd) {
    extern __shared__ __align__(1024) char smem[];
    const uint32_t sb = smem_u32(smem);
    const int tid = threadIdx.x, lane = tid & 31, wid = tid >> 5;
    const int m0 = blockIdx.y * 128, n0 = blockIdx.x * 128;
    const int wm = (wid >> 1) * 64, wn = (wid & 1) * 64;

    const int lrow = tid >> 3, lu = tid & 7;   // lrow 0..15
    const float* srcA = A + (size_t)(m0 + lrow) * lda + lu * 4;
    const float* srcB = Bt + (size_t)(n0 + lrow) * ldb + lu * 4;
    const size_t rstepA = (size_t)16 * lda, rstepB = (size_t)16 * ldb;
    const uint32_t d0 = (uint32_t)lrow * 128 + (((uint32_t)(lu ^ (lrow & 7))) << 4);

    const uint32_t asel = lane >> 4;
    const uint32_t bsel = (lane >> 3) & 1;
    const uint32_t swz = lane & 7;
    const uint32_t a_ro = (uint32_t)(wm + (lane & 7) + ((lane >> 3) & 1) * 8) * 128;
    const uint32_t b_ro = (uint32_t)(wn + (lane & 7) + (lane >> 4) * 8) * 128;

    float acc[4][8][4];
#pragma unroll
    for (int i = 0; i < 4; i++)
#pragma unroll
        for (int j = 0; j < 8; j++)
#pragma unroll
            for (int c = 0; c < 4; c++) acc[i][j][c] = 0.f;

    const int KT = K >> 5;

#define LOADC3(s, kof)                                                         \
    do {                                                                       \
        uint32_t bA = sb + (uint32_t)(s) * STG3;                               \
        uint32_t bB = bA + 16384;                                              \
        const float* pa = srcA + (kof);                                        \
        const float* pb = srcB + (kof);                                        \
        _Pragma("unroll") for (int ii = 0; ii < 8; ii++)                       \
            cp16(bA + d0 + ii * 2048, pa + ii * rstepA);                       \
        _Pragma("unroll") for (int ii = 0; ii < 8; ii++)                       \
            cp16(bB + d0 + ii * 2048, pb + ii * rstepB);                       \
        asm volatile("cp.async.commit_group;" ::: "memory");                   \
    } while (0)

    LOADC3(0, 0);
    LOADC3(1, 32);

    int stage = 0;
    for (int i = 0; i < KT; i++) {
        if (i < KT - 1)
            asm volatile("cp.async.wait_group 1;" ::: "memory");
        else
            asm volatile("cp.async.wait_group 0;" ::: "memory");
        __syncthreads();
        if (i + 2 < KT) {
            int ns = stage + 2;
            if (ns >= 3) ns -= 3;
            LOADC3(ns, (size_t)(i + 2) * 32);
        }
        const uint32_t sA = sb + (uint32_t)stage * STG3;
        const uint32_t sB = sA + 16384;
#pragma unroll
        for (int ks = 0; ks < 4; ks++) {
            const uint32_t va = ((2u * ks + asel) ^ swz) << 4;
            const uint32_t vb = ((2u * ks + bsel) ^ swz) << 4;
            uint32_t af[4][4];
#pragma unroll
            for (int ii = 0; ii < 4; ii++)
                LDSM4(af[ii], sA + a_ro + ii * 2048 + va);
            uint32_t bf[8][2];
#pragma unroll
            for (int nb = 0; nb < 4; nb++) {
                uint32_t r[4];
                LDSM4(r, sB + b_ro + nb * 2048 + vb);
                bf[2 * nb][0] = r[0]; bf[2 * nb][1] = r[1];
                bf[2 * nb + 1][0] = r[2]; bf[2 * nb + 1][1] = r[3];
            }
#pragma unroll
            for (int ii = 0; ii < 4; ii++)
#pragma unroll
                for (int j = 0; j < 8; j++) MMA_TF32(acc[ii][j], af[ii], bf[j]);
        }
        stage++;
        if (stage == 3) stage = 0;
    }

#pragma unroll
    for (int i = 0; i < 4; i++) {
        int r0 = m0 + wm + i * 16 + (lane >> 2);
#pragma unroll
        for (int j = 0; j < 8; j++) {
            int c0 = n0 + wn + j * 8 + (lane & 3) * 2;
            float v0 = acc[i][j][0], v1 = acc[i][j][1];
            float v2 = acc[i][j][2], v3 = acc[i][j][3];
            if (bias) {
                float b0 = bias[c0], b1 = bias[c0 + 1];
                v0 += b0; v1 += b1; v2 += b0; v3 += b1;
            }
            if (relu) {
                v0 = fmaxf(v0, 0.f); v1 = fmaxf(v1, 0.f);
                v2 = fmaxf(v2, 0.f); v3 = fmaxf(v3, 0.f);
            }
            size_t o0 = (size_t)r0 * N + c0;
            size_t o1 = (size_t)(r0 + 8) * N + c0;
            if (res) {
                v0 += res[o0]; v1 += res[o0 + 1];
                v2 += res[o1]; v3 += res[o1 + 1];
            }
            if (rnd) {
                v0 = rtf32(v0); v1 = rtf32(v1);
                v2 = rtf32(v2); v3 = rtf32(v3);
            }
            C[o0] = v0; C[o0 + 1] = v1;
            C[o1] = v2; C[o1 + 1] = v3;
        }
    }
#undef LOADC3
}

// ---------------------------------------------------------------------------
// tf32 mma.sync GEMM (attention S = Q K^T): batched, causal skip. 128x128,
// 256 threads.
// ---------------------------------------------------------------------------
#define STG 32768
#define GEMM_SMEM (3 * STG)

__global__ __launch_bounds__(256, 2) void hgemm(
    const float* __restrict__ A, int lda, size_t zsA1, size_t zsA0,
    const float* __restrict__ Bt, int ldb, size_t zsB1, size_t zsB0,
    float* __restrict__ C, size_t zsC1, size_t zsC0,
    int M, int N, int K, int causal) {
    extern __shared__ __align__(1024) char smem[];
    const int m0 = blockIdx.y * 128, n0 = blockIdx.x * 128;
    if (causal && n0 > m0 + 127) return;
    const int z1 = blockIdx.z >> 4, z0 = blockIdx.z & 15;
    A += (size_t)z1 * zsA1 + (size_t)z0 * zsA0;
    Bt += (size_t)z1 * zsB1 + (size_t)z0 * zsB0;
    C += (size_t)z1 * zsC1 + (size_t)z0 * zsC0;

    const uint32_t sb = smem_u32(smem);
    const int tid = threadIdx.x, lane = tid & 31, wid = tid >> 5;
    const int wm = (wid >> 1) * 32, wn = (wid & 1) * 64;

    const int lrow = tid >> 3, lu = tid & 7;
    const float* srcA = A + (size_t)(m0 + lrow) * lda + lu * 4;
    const float* srcB = Bt + (size_t)(n0 + lrow) * ldb + lu * 4;
    const size_t rstepA = (size_t)32 * lda, rstepB = (size_t)32 * ldb;
    const uint32_t d0 = (uint32_t)lrow * 128 + (((uint32_t)(lu ^ (lrow & 7))) << 4);

    const uint32_t asel = lane >> 4;
    const uint32_t bsel = (lane >> 3) & 1;
    const uint32_t swz = lane & 7;
    const uint32_t a_ro = (uint32_t)(wm + (lane & 7) + ((lane >> 3) & 1) * 8) * 128;
    const uint32_t b_ro = (uint32_t)(wn + (lane & 7) + (lane >> 4) * 8) * 128;

    float acc[2][8][4];
#pragma unroll
    for (int i = 0; i < 2; i++)
#pragma unroll
        for (int j = 0; j < 8; j++)
#pragma unroll
            for (int c = 0; c < 4; c++) acc[i][j][c] = 0.f;

    const int KT = K >> 5;

#define LOADC(s, kof)                                                          \
    do {                                                                       \
        uint32_t bA = sb + (uint32_t)(s) * STG;                                \
        uint32_t bB = bA + 16384;                                              \
        const float* pa = srcA + (kof);                                        \
        const float* pb = srcB + (kof);                                        \
        _Pragma("unroll") for (int ii = 0; ii < 4; ii++)                       \
            cp16(bA + d0 + ii * 4096, pa + ii * rstepA);                       \
        _Pragma("unroll") for (int ii = 0; ii < 4; ii++)                       \
            cp16(bB + d0 + ii * 4096, pb + ii * rstepB);                       \
        asm volatile("cp.async.commit_group;" ::: "memory");                   \
    } while (0)

    LOADC(0, 0);
    LOADC(1, 32);

    int stage = 0;
    for (int i = 0; i < KT; i++) {
        if (i < KT - 1)
            asm volatile("cp.async.wait_group 1;" ::: "memory");
        else
            asm volatile("cp.async.wait_group 0;" ::: "memory");
        __syncthreads();
        if (i + 2 < KT) {
            int ns = stage + 2;
            if (ns >= 3) ns -= 3;
            LOADC(ns, (size_t)(i + 2) * 32);
        }
        const uint32_t sA = sb + (uint32_t)stage * STG;
        const uint32_t sB = sA + 16384;
#pragma unroll
        for (int ks = 0; ks < 4; ks++) {
            const uint32_t va = ((2u * ks + asel) ^ swz) << 4;
            const uint32_t vb = ((2u * ks + bsel) ^ swz) << 4;
            uint32_t af[2][4];
            LDSM4(af[0], sA + a_ro + va);
            LDSM4(af[1], sA + a_ro + 2048 + va);
            uint32_t bf[8][2];
#pragma unroll
            for (int nb = 0; nb < 4; nb++) {
                uint32_t r[4];
                LDSM4(r, sB + b_ro + nb * 2048 + vb);
                bf[2 * nb][0] = r[0]; bf[2 * nb][1] = r[1];
                bf[2 * nb + 1][0] = r[2]; bf[2 * nb + 1][1] = r[3];
            }
#pragma unroll
            for (int ii = 0; ii < 2; ii++)
#pragma unroll
                for (int j = 0; j < 8; j++) MMA_TF32(acc[ii][j], af[ii], bf[j]);
        }
        stage++;
        if (stage == 3) stage = 0;
    }

#pragma unroll
    for (int i = 0; i < 2; i++) {
        int r0 = m0 + wm + i * 16 + (lane >> 2);
#pragma unroll
        for (int j = 0; j < 8; j++) {
            int c0 = n0 + wn + j * 8 + (lane & 3) * 2;
            size_t o0 = (size_t)r0 * N + c0;
            size_t o1 = (size_t)(r0 + 8) * N + c0;
            C[o0] = acc[i][j][0]; C[o0 + 1] = acc[i][j][1];
            C[o1] = acc[i][j][2]; C[o1 + 1] = acc[i][j][3];
        }
    }
#undef LOADC
}

// ---------------------------------------------------------------------------
// Softmax over S rows: warp per row, single online max+sum pass + write pass.
// Writes tf32 P in place, zero-fill up to row's 128-aligned width.
// ---------------------------------------------------------------------------
__global__ __launch_bounds__(256) void softmax_kernel() {
    int gid = blockIdx.x * 8 + (threadIdx.x >> 5);
    int lane = threadIdx.x & 31;
    int z = gid >> 10, i = gid & 1023;
    float* sr = g_s + (size_t)z * (TT * TT) + (size_t)i * TT;
    int L = i + 1;
    int W = ((i >> 7) + 1) << 7;
    float m = -1e30f, s = 0.f;
    for (int j0 = lane * 4; j0 < W; j0 += 128) {
        float4 v = *(const float4*)(sr + j0);
        float e[4] = {v.x, v.y, v.z, v.w};
#pragma unroll
        for (int k = 0; k < 4; k++) {
            if (j0 + k < L) {
                float val = e[k] * 0.125f;
                if (val > m) {
                    s = s * __expf(m - val) + 1.f;
                    m = val;
                } else {
                    s += __expf(val - m);
                }
            }
        }
    }
    float M = warpMax(m);
    s *= __expf(m - M);
    float inv = 1.f / warpSum(s);
    for (int j0 = lane * 4; j0 < W; j0 += 128) {
        float4 v = *(const float4*)(sr + j0);
        float4 p;
        p.x = (j0 + 0 < L) ? rtf32(__expf(v.x * 0.125f - M) * inv) : 0.f;
        p.y = (j0 + 1 < L) ? rtf32(__expf(v.y * 0.125f - M) * inv) : 0.f;
        p.z = (j0 + 2 < L) ? rtf32(__expf(v.z * 0.125f - M) * inv) : 0.f;
        p.w = (j0 + 3 < L) ? rtf32(__expf(v.w * 0.125f - M) * inv) : 0.f;
        *(float4*)(sr + j0) = p;
    }
}

// ---------------------------------------------------------------------------
// PV gemm: O[128m x 64n] = P[m,k] * Vt[n,k]^T per (z, m-block), causal
// K truncation. 128 threads, 3-stage cp.async.
// ---------------------------------------------------------------------------
#define PV_STG 24576
#define PV_SMEM (3 * PV_STG)

__global__ __launch_bounds__(128, 2) void pv_gemm() {
    extern __shared__ __align__(1024) char smem[];
    const uint32_t sb = smem_u32(smem);
    const int tid = threadIdx.x, lane = tid & 31, wid = tid >> 5;
    const int mb = blockIdx.x, z = blockIdx.y;
    const int m0 = mb * 128;
    const int KT = (mb + 1) * 4;

    const float* P = g_s + (size_t)z * (TT * TT);
    const float* Vt = g_vt + (size_t)z * (HS * TT);

    const int lrow = tid >> 3, lu = tid & 7;
    const float* srcA = P + (size_t)(m0 + lrow) * TT + lu * 4;
    const float* srcB = Vt + (size_t)lrow * TT + lu * 4;
    const uint32_t d0 = (uint32_t)lrow * 128 + (((uint32_t)(lu ^ (lrow & 7))) << 4);

    const uint32_t asel = lane >> 4;
    const uint32_t bsel = (lane >> 3) & 1;
    const uint32_t swz = lane & 7;
    const int wm = wid * 32;
    const uint32_t a_ro = (uint32_t)(wm + (lane & 7) + ((lane >> 3) & 1) * 8) * 128;
    const uint32_t b_ro = (uint32_t)((lane & 7) + (lane >> 4) * 8) * 128;

    float acc[2][8][4];
#pragma unroll
    for (int i = 0; i < 2; i++)
#pragma unroll
        for (int j = 0; j < 8; j++)
#pragma unroll
            for (int c = 0; c < 4; c++) acc[i][j][c] = 0.f;

#define PLOADC(s, kof)                                                         \
    do {                                                                       \
        uint32_t bA = sb + (uint32_t)(s) * PV_STG;                             \
        uint32_t bB = bA + 16384;                                              \
        const float* pa = srcA + (kof);                                        \
        const float* pb = srcB + (kof);                                        \
        _Pragma("unroll") for (int ii = 0; ii < 8; ii++)                       \
            cp16(bA + d0 + ii * 2048, pa + (size_t)ii * 16 * TT);              \
        _Pragma("unroll") for (int ii = 0; ii < 4; ii++)                       \
            cp16(bB + d0 + ii * 2048, pb + (size_t)ii * 16 * TT);              \
        asm volatile("cp.async.commit_group;" ::: "memory");                   \
    } while (0)

    PLOADC(0, 0);
    PLOADC(1, 32);

    int stage = 0;
    for (int i = 0; i < KT; i++) {
        if (i < KT - 1)
            asm volatile("cp.async.wait_group 1;" ::: "memory");
        else
            asm volatile("cp.async.wait_group 0;" ::: "memory");
        __syncthreads();
        if (i + 2 < KT) {
            int ns = stage + 2;
            if (ns >= 3) ns -= 3;
            PLOADC(ns, (size_t)(i + 2) * 32);
        }
        const uint32_t sA = sb + (uint32_t)stage * PV_STG;
        const uint32_t sB = sA + 16384;
#pragma unroll
        for (int ks = 0; ks < 4; ks++) {
            const uint32_t va = ((2u * ks + asel) ^ swz) << 4;
            const uint32_t vb = ((2u * ks + bsel) ^ swz) << 4;
            uint32_t af[2][4];
            LDSM4(af[0], sA + a_ro + va);
            LDSM4(af[1], sA + a_ro + 2048 + va);
            uint32_t bf[8][2];
#pragma unroll
            for (int nb = 0; nb < 4; nb++) {
                uint32_t r[4];
                LDSM4(r, sB + b_ro + nb * 2048 + vb);
                bf[2 * nb][0] = r[0]; bf[2 * nb][1] = r[1];
                bf[2 * nb + 1][0] = r[2]; bf[2 * nb + 1][1] = r[3];
            }
#pragma unroll
            for (int ii = 0; ii < 2; ii++)
#pragma unroll
                for (int j = 0; j < 8; j++) MMA_TF32(acc[ii][j], af[ii], bf[j]);
        }
        stage++;
        if (stage == 3) stage = 0;
    }

    const int b = z >> 4, h = z & 15;
#pragma unroll
    for (int i = 0; i < 2; i++) {
        int r0 = m0 + wm + i * 16 + (lane >> 2);
        int tok0 = b * TT + r0;
#pragma unroll
        for (int j = 0; j < 8; j++) {
            int c0 = h * 64 + j * 8 + (lane & 3) * 2;
            size_t o0 = (size_t)tok0 * DM + c0;
            size_t o1 = (size_t)(tok0 + 8) * DM + c0;
            g_ao[o0] = rtf32(acc[i][j][0]);
            g_ao[o0 + 1] = rtf32(acc[i][j][1]);
            g_ao[o1] = rtf32(acc[i][j][2]);
            g_ao[o1 + 1] = rtf32(acc[i][j][3]);
        }
    }
#undef PLOADC
}

// ---------------------------------------------------------------------------
// Loss: single-pass online softmax per row (float4 reads), deterministic mean
// ---------------------------------------------------------------------------
__global__ __launch_bounds__(256) void loss_row_kernel(const float* __restrict__ logits,
                                                       const int* __restrict__ targets) {
    int row = blockIdx.x, tid = threadIdx.x;
    const float4* lr4 = (const float4*)(logits + (size_t)row * VV);
    float m = -1e30f, s = 0.f;
    for (int c = tid; c < VV / 4; c += 256) {
        float4 v = lr4[c];
        float vm = fmaxf(fmaxf(v.x, v.y), fmaxf(v.z, v.w));
        float nm = fmaxf(m, vm);
        s = s * __expf(m - nm) + __expf(v.x - nm) + __expf(v.y - nm) +
            __expf(v.z - nm) + __expf(v.w - nm);
        m = nm;
    }
    float M = blockReduceMax(m);
    s *= __expf(m - M);
    float S = blockReduceSum(s);
    if (tid == 0)
        g_rowloss[row] = (M + logf(S)) - logits[(size_t)row * VV + targets[row]];
}

__global__ __launch_bounds__(256) void loss_final_kernel(float* __restrict__ out) {
    float s = 0.f;
    for (int i = threadIdx.x; i < NP; i += 256) s += g_rowloss[i];
    s = blockReduceSum(s);
    if (threadIdx.x == 0) out[0] = s * (1.f / NP);
}

// ---------------------------------------------------------------------------
// Host launcher
// ---------------------------------------------------------------------------
extern "C" void kernel_launch(void* const* d_in, const int* in_sizes, int n_in,
                              void* d_out, int out_size) {
    const int*   idx  = (const int*)d_in[0];
    const int*   ibx  = (const int*)d_in[1];
    const int*   tgt  = (const int*)d_in[2];
    const float* tok  = (const float*)d_in[3];
    const float* pos  = (const float*)d_in[4];
    const float* book = (const float*)d_in[5];
    const float* Wq   = (const float*)d_in[6];
    const float* Wk   = (const float*)d_in[7];
    const float* Wv   = (const float*)d_in[8];
    const float* Wo   = (const float*)d_in[9];
    const float* bo   = (const float*)d_in[10];
    const float* ln1s = (const float*)d_in[11];
    const float* ln1b = (const float*)d_in[12];
    const float* ln2s = (const float*)d_in[13];
    const float* ln2b = (const float*)d_in[14];
    const float* W1   = (const float*)d_in[15];
    const float* b1   = (const float*)d_in[16];
    const float* W2   = (const float*)d_in[17];
    const float* b2   = (const float*)d_in[18];
    const float* lnfs = (const float*)d_in[19];
    const float* lnfb = (const float*)d_in[20];
    const float* Wh   = (const float*)d_in[21];
    const float* bh   = (const float*)d_in[22];
    float* out = (float*)d_out;

    float *x, *qkv, *s_, *wt, *h, *ao, *h2, *ff;
    cudaGetSymbolAddress((void**)&x,   g_x);
    cudaGetSymbolAddress((void**)&qkv, g_qkv);
    cudaGetSymbolAddress((void**)&s_,  g_s);
    cudaGetSymbolAddress((void**)&wt,  g_wt);
    cudaGetSymbolAddress((void**)&h,   g_h);
    cudaGetSymbolAddress((void**)&ao,  g_ao);
    cudaGetSymbolAddress((void**)&h2,  g_h2);
    cudaGetSymbolAddress((void**)&ff,  g_ff);

    cudaFuncSetAttribute(hgemm, cudaFuncAttributeMaxDynamicSharedMemorySize,
                         GEMM_SMEM);
    cudaFuncSetAttribute(hgemm3, cudaFuncAttributeMaxDynamicSharedMemorySize,
                         GEMM3_SMEM);
    cudaFuncSetAttribute(pv_gemm, cudaFuncAttributeMaxDynamicSharedMemorySize,
                         PV_SMEM);

    wtr_all_kernel<<<TIL_TOTAL, 256>>>(Wq, Wk, Wv, Wo, W1, W2, Wh, wt);
    embed_kernel<<<NP * DM / 1024, 256>>>(idx, tok, pos);

    const size_t sAb = (size_t)TT * QKVN;      // per-b stride into qkv rows
    const size_t sCb = (size_t)HH * TT * TT;   // per-b stride into g_s
    for (int l = 0; l < LL; l++) {
        ln_kernel<<<NP / 8, 256>>>(x, ln1s + l * DM, ln1b + l * DM, h, DM);
        hgemm3<<<dim3(QKVN / 128, NP / 128), 128, GEMM3_SMEM>>>(
            h, DM, wt + OFF_QKV + (size_t)l * 3 * DM * DM, DM,
            nullptr, nullptr, qkv, NP, QKVN, DM, 0, 1);
        vt_kernel<<<dim3(TT / 64, ZZ), 256>>>();
        hgemm<<<dim3(TT / 128, TT / 128, ZZ), 256, GEMM_SMEM>>>(
            qkv, QKVN, sAb, 64, qkv + 1024, QKVN, sAb, 64,
            s_, sCb, (size_t)TT * TT, TT, TT, HS, 1);
        if (l == 0) book_kernel<<<NP * DBK / 256, 256>>>(ibx, book);
        softmax_kernel<<<ZZ * TT / 8, 256>>>();
        pv_gemm<<<dim3(TT / 128, ZZ), 128, PV_SMEM>>>();
        hgemm3<<<dim3(DM / 128, NP / 128), 128, GEMM3_SMEM>>>(
            ao, DM, wt + OFF_WO + (size_t)l * DM * DM, DM,
            bo + l * DM, x, x, NP, DM, DM, 0, 0);
        ln_kernel<<<NP / 8, 256>>>(x, ln2s + l * DM, ln2b + l * DM, h2, DIN);
        hgemm3<<<dim3(DFF / 128, NP / 128), 128, GEMM3_SMEM>>>(
            h2, DIN, wt + OFF_W1 + (size_t)l * DFF * DIN, DIN,
            b1 + l * DFF, nullptr, ff, NP, DFF, DIN, 1, 1);
        hgemm3<<<dim3(DM / 128, NP / 128), 128, GEMM3_SMEM>>>(
            ff, DFF, wt + OFF_W2 + (size_t)l * DM * DFF, DFF,
            b2 + l * DM, x, x, NP, DM, DFF, 0, 0);
    }

    ln_kernel<<<NP / 8, 256>>>(x, lnfs, lnfb, h, DM);
    hgemm3<<<dim3(VV / 128, NP / 128), 128, GEMM3_SMEM>>>(
        h, DM, wt + OFF_WH, DM, bh, nullptr, out, NP, VV, DM, 0, 0);
    loss_row_kernel<<<NP, 256>>>(out, tgt);
    if (out_size > NP * VV)
        loss_final_kernel<<<1, 256>>>(out + (size_t)NP * VV);
}

// round 15
// speedup vs baseline: 1.0033x; 1.0033x over previous
#include <cuda_runtime.h>
#include <math.h>
#include <stdint.h>

// ---------------------------------------------------------------------------
// Model dims
// ---------------------------------------------------------------------------
#define NP   4096
#define BB   4
#define TT   1024
#define DM   1024
#define HH   16
#define HS   64
#define DFF  4096
#define LL   6
#define VV   32000
#define DBK  64
#define DIN  1088
#define QKVN 3072
#define ZZ   (BB * HH)          /* 64 (b,h) pairs */

// Weight arena offsets (elements)
#define OFF_QKV 0ull
#define OFF_WO  18874368ull
#define OFF_W1  25165824ull
#define OFF_W2  51904512ull
#define OFF_WH  77070336ull
#define WT_TOTAL 109838336ull

// Fused transpose tile counts (64x64 tiles)
#define TIL_SQ   256
#define TIL_W1   1088
#define TIL_W2   1024
#define TIL_LAYER (4 * TIL_SQ + TIL_W1 + TIL_W2)
#define TIL_WH   8000
#define TIL_TOTAL (LL * TIL_LAYER + TIL_WH)

// ---------------------------------------------------------------------------
// Scratch
// ---------------------------------------------------------------------------
__device__ __align__(128) float g_x  [NP * DM];
__device__ __align__(128) float g_h  [NP * DM];
__device__ __align__(128) float g_qkv[NP * QKVN];
__device__ __align__(128) float g_ao [NP * DM];
__device__ __align__(128) float g_h2 [NP * DIN];
__device__ __align__(128) float g_ff [NP * DFF];
__device__ __align__(128) float g_wt [WT_TOTAL];
__device__ __align__(128) float g_s  [(size_t)ZZ * TT * TT];   // attention scores
__device__ __align__(128) float g_vt [(size_t)ZZ * HS * TT];   // V^T per (b,h)
__device__ float g_rowloss[NP];

// ---------------------------------------------------------------------------
// Helpers
// ---------------------------------------------------------------------------
__device__ __forceinline__ uint32_t smem_u32(const void* p) {
    uint32_t a;
    asm("{ .reg .u64 t; cvta.to.shared.u64 t, %1; cvt.u32.u64 %0, t; }"
        : "=r"(a) : "l"(p));
    return a;
}

__device__ __forceinline__ float rtf32(float x) {
    uint32_t u;
    asm("cvt.rna.tf32.f32 %0, %1;" : "=r"(u) : "f"(x));
    return __uint_as_float(u);
}

__device__ __forceinline__ void cp16(uint32_t dst, const void* src) {
    asm volatile("cp.async.cg.shared.global [%0], [%1], 16;" ::"r"(dst), "l"(src));
}

#define LDSM4(r, a)                                                            \
    asm volatile("ldmatrix.sync.aligned.m8n8.x4.shared.b16 {%0,%1,%2,%3}, [%4];" \
                 : "=r"((r)[0]), "=r"((r)[1]), "=r"((r)[2]), "=r"((r)[3])      \
                 : "r"(a))

#define MMA_TF32(d, a, b)                                                      \
    asm volatile(                                                              \
        "mma.sync.aligned.m16n8k8.row.col.f32.tf32.tf32.f32 "                  \
        "{%0,%1,%2,%3}, {%4,%5,%6,%7}, {%8,%9}, {%0,%1,%2,%3};\n"              \
        : "+f"(d[0]), "+f"(d[1]), "+f"(d[2]), "+f"(d[3])                       \
        : "r"(a[0]), "r"(a[1]), "r"(a[2]), "r"(a[3]), "r"(b[0]), "r"(b[1]))

__device__ __forceinline__ float warpSum(float v) {
#pragma unroll
    for (int o = 16; o; o >>= 1) v += __shfl_xor_sync(0xffffffffu, v, o);
    return v;
}
__device__ __forceinline__ float warpMax(float v) {
#pragma unroll
    for (int o = 16; o; o >>= 1) v = fmaxf(v, __shfl_xor_sync(0xffffffffu, v, o));
    return v;
}

__device__ __forceinline__ float blockReduceSum(float v) {
    __shared__ float sm[33];
    int lane = threadIdx.x & 31, w = threadIdx.x >> 5;
    v = warpSum(v);
    if (lane == 0) sm[w] = v;
    __syncthreads();
    if (w == 0) {
        v = (lane < (blockDim.x >> 5)) ? sm[lane] : 0.f;
        v = warpSum(v);
        if (lane == 0) sm[32] = v;
    }
    __syncthreads();
    return sm[32];
}
__device__ __forceinline__ float blockReduceMax(float v) {
    __shared__ float sm[33];
    int lane = threadIdx.x & 31, w = threadIdx.x >> 5;
    v = warpMax(v);
    if (lane == 0) sm[w] = v;
    __syncthreads();
    if (w == 0) {
        v = (lane < (blockDim.x >> 5)) ? sm[lane] : -1e30f;
        v = warpMax(v);
        if (lane == 0) sm[32] = v;
    }
    __syncthreads();
    return sm[32];
}

// ---------------------------------------------------------------------------
// Elementwise kernels
// ---------------------------------------------------------------------------
__global__ void embed_kernel(const int* __restrict__ idx,
                             const float* __restrict__ tok,
                             const float* __restrict__ pos) {
    int gid = blockIdx.x * 256 + threadIdx.x;
    int n = gid >> 8, c4 = (gid & 255) * 4;
    int t = n & (TT - 1);
    const float4 a = *(const float4*)(tok + (size_t)idx[n] * DM + c4);
    const float4 b = *(const float4*)(pos + (size_t)t * DM + c4);
    float4 o;
    o.x = a.x + b.x; o.y = a.y + b.y; o.z = a.z + b.z; o.w = a.w + b.w;
    *(float4*)(g_x + (size_t)n * DM + c4) = o;
}

__global__ void book_kernel(const int* __restrict__ ibx,
                            const float* __restrict__ book) {
    int gid = blockIdx.x * 256 + threadIdx.x;
    int n = gid >> 6, d = gid & 63, b = n >> 10;
    g_h2[(size_t)n * DIN + DM + d] = rtf32(book[ibx[b] * DBK + d]);
}

// LayerNorm: warp per row, 4 rows/block.
__global__ __launch_bounds__(128) void ln_kernel(
    const float* __restrict__ x, const float* __restrict__ sc,
    const float* __restrict__ bi, float* __restrict__ y, int ldo) {
    int warp = threadIdx.x >> 5, lane = threadIdx.x & 31;
    int row = blockIdx.x * 4 + warp;
    const float4* xr = (const float4*)(x + (size_t)row * DM);
    float4 v[8];
    float sum = 0.f;
#pragma unroll
    for (int i = 0; i < 8; i++) {
        v[i] = xr[i * 32 + lane];
        sum += v[i].x + v[i].y + v[i].z + v[i].w;
    }
    float mu = warpSum(sum) * (1.f / DM);
    float sq = 0.f;
#pragma unroll
    for (int i = 0; i < 8; i++) {
        float dx = v[i].x - mu, dy = v[i].y - mu;
        float dz = v[i].z - mu, dw = v[i].w - mu;
        sq += dx * dx + dy * dy + dz * dz + dw * dw;
    }
    float rstd = rsqrtf(warpSum(sq) * (1.f / DM) + 1e-5f);
#pragma unroll
    for (int i = 0; i < 8; i++) {
        int c4 = i * 32 + lane;
        float4 s4 = ((const float4*)sc)[c4];
        float4 b4 = ((const float4*)bi)[c4];
        float4 o;
        o.x = rtf32((v[i].x - mu) * rstd * s4.x + b4.x);
        o.y = rtf32((v[i].y - mu) * rstd * s4.y + b4.y);
        o.z = rtf32((v[i].z - mu) * rstd * s4.z + b4.z);
        o.w = rtf32((v[i].w - mu) * rstd * s4.w + b4.w);
        *(float4*)(y + (size_t)row * ldo + c4 * 4) = o;
    }
}

// ---------------------------------------------------------------------------
// Fused weight transpose + tf32 round (one launch for all weights)
// ---------------------------------------------------------------------------
__device__ __forceinline__ void wtr_tile(const float* __restrict__ W,
                                         float* __restrict__ Wt, int K, int N,
                                         int tile) {
    __shared__ float s[64][65];
    int tiles_n = N >> 6;
    int n0 = (tile % tiles_n) << 6;
    int k0 = (tile / tiles_n) << 6;
    int t = threadIdx.x;
    int kk = t >> 4, nn4 = (t & 15) * 4;
#pragma unroll
    for (int i = 0; i < 4; i++) {
        int k = kk + 16 * i;
        float4 w = *(const float4*)(W + (size_t)(k0 + k) * N + n0 + nn4);
        s[nn4 + 0][k] = w.x;
        s[nn4 + 1][k] = w.y;
        s[nn4 + 2][k] = w.z;
        s[nn4 + 3][k] = w.w;
    }
    __syncthreads();
    int k4 = (t & 15) * 4;
#pragma unroll
    for (int i = 0; i < 4; i++) {
        int n = (t >> 4) + 16 * i;
        float4 o;
        o.x = rtf32(s[n][k4 + 0]);
        o.y = rtf32(s[n][k4 + 1]);
        o.z = rtf32(s[n][k4 + 2]);
        o.w = rtf32(s[n][k4 + 3]);
        *(float4*)(Wt + (size_t)(n0 + n) * K + k0 + k4) = o;
    }
}

__global__ __launch_bounds__(256) void wtr_all_kernel(
    const float* __restrict__ Wq, const float* __restrict__ Wk,
    const float* __restrict__ Wv, const float* __restrict__ Wo,
    const float* __restrict__ W1, const float* __restrict__ W2,
    const float* __restrict__ Wh, float* __restrict__ wt) {
    int b = blockIdx.x;
    if (b < LL * TIL_LAYER) {
        int l = b / TIL_LAYER, r = b % TIL_LAYER;
        if (r < 4 * TIL_SQ) {
            int w = r >> 8, tile = r & 255;
            const float* src;
            float* dst;
            size_t lofs = (size_t)l * DM * DM;
            if (w == 0) {
                src = Wq + lofs;
                dst = wt + OFF_QKV + (size_t)l * 3 * DM * DM;
            } else if (w == 1) {
                src = Wk + lofs;
                dst = wt + OFF_QKV + (size_t)l * 3 * DM * DM + (size_t)DM * DM;
            } else if (w == 2) {
                src = Wv + lofs;
                dst = wt + OFF_QKV + (size_t)l * 3 * DM * DM + 2ull * DM * DM;
            } else {
                src = Wo + lofs;
                dst = wt + OFF_WO + lofs;
            }
            wtr_tile(src, dst, DM, DM, tile);
        } else if (r < 4 * TIL_SQ + TIL_W1) {
            wtr_tile(W1 + (size_t)l * DIN * DFF, wt + OFF_W1 + (size_t)l * DFF * DIN,
                     DIN, DFF, r - 4 * TIL_SQ);
        } else {
            wtr_tile(W2 + (size_t)l * DFF * DM, wt + OFF_W2 + (size_t)l * DM * DFF,
                     DFF, DM, r - 4 * TIL_SQ - TIL_W1);
        }
    } else {
        wtr_tile(Wh, wt + OFF_WH, DM, VV, b - LL * TIL_LAYER);
    }
}

// V^T: qkv V-part -> g_vt[z][d][j]  (z = b*16+h)
__global__ __launch_bounds__(256) void vt_kernel() {
    __shared__ float s[64][65];
    int z = blockIdx.y, jt = blockIdx.x;
    int b = z >> 4, h = z & 15;
    int t = threadIdx.x;
    int rr = t >> 4, c4 = (t & 15) * 4;
#pragma unroll
    for (int i = 0; i < 4; i++) {
        int r = rr + 16 * i;
        const float4 w = *(const float4*)(g_qkv +
            (size_t)(b * TT + jt * 64 + r) * QKVN + 2048 + h * 64 + c4);
        s[c4 + 0][r] = w.x;
        s[c4 + 1][r] = w.y;
        s[c4 + 2][r] = w.z;
        s[c4 + 3][r] = w.w;
    }
    __syncthreads();
#pragma unroll
    for (int i = 0; i < 4; i++) {
        int d = rr + 16 * i;
        float4 o;
        o.x = s[d][c4 + 0];
        o.y = s[d][c4 + 1];
        o.z = s[d][c4 + 2];
        o.w = s[d][c4 + 3];
        *(float4*)(g_vt + (size_t)z * (HS * TT) + (size_t)d * TT + jt * 64 + c4) = o;
    }
}

// ---------------------------------------------------------------------------
// hgemm3: linear-layer tf32 GEMM. 128x128 CTA tile, 128 threads (4 warps,
// warp tile 64x64), BK=32, 3-stage cp.async, 2 CTA/SM.
// ---------------------------------------------------------------------------
#define STG3 32768
#define GEMM3_SMEM (3 * STG3)

__global__ __launch_bounds__(128, 2) void hgemm3(
    const float* __restrict__ A, int lda,
    const float* __restrict__ Bt, int ldb,
    const float* __restrict__ bias, const float* __restrict__ res,
    float* __restrict__ C, int M, int N, int K, int relu, int rnd) {
    extern __shared__ __align__(1024) char smem[];
    const uint32_t sb = smem_u32(smem);
    const int tid = threadIdx.x, lane = tid & 31, wid = tid >> 5;
    const int m0 = blockIdx.y * 128, n0 = blockIdx.x * 128;
    const int wm = (wid >> 1) * 64, wn = (wid & 1) * 64;

    const int lrow = tid >> 3, lu = tid & 7;   // lrow 0..15
    const float* srcA = A + (size_t)(m0 + lrow) * lda + lu * 4;
    const float* srcB = Bt + (size_t)(n0 + lrow) * ldb + lu * 4;
    const size_t rstepA = (size_t)16 * lda, rstepB = (size_t)16 * ldb;
    const uint32_t d0 = (uint32_t)lrow * 128 + (((uint32_t)(lu ^ (lrow & 7))) << 4);

    const uint32_t asel = lane >> 4;
    const uint32_t bsel = (lane >> 3) & 1;
    const uint32_t swz = lane & 7;
    const uint32_t a_ro = (uint32_t)(wm + (lane & 7) + ((lane >> 3) & 1) * 8) * 128;
    const uint32_t b_ro = (uint32_t)(wn + (lane & 7) + (lane >> 4) * 8) * 128;

    float acc[4][8][4];
#pragma unroll
    for (int i = 0; i < 4; i++)
#pragma unroll
        for (int j = 0; j < 8; j++)
#pragma unroll
            for (int c = 0; c < 4; c++) acc[i][j][c] = 0.f;

    const int KT = K >> 5;

#define LOADC3(s, kof)                                                         \
    do {                                                                       \
        uint32_t bA = sb + (uint32_t)(s) * STG3;                               \
        uint32_t bB = bA + 16384;                                              \
        const float* pa = srcA + (kof);                                        \
        const float* pb = srcB + (kof);                                        \
        _Pragma("unroll") for (int ii = 0; ii < 8; ii++)                       \
            cp16(bA + d0 + ii * 2048, pa + ii * rstepA);                       \
        _Pragma("unroll") for (int ii = 0; ii < 8; ii++)                       \
            cp16(bB + d0 + ii * 2048, pb + ii * rstepB);                       \
        asm volatile("cp.async.commit_group;" ::: "memory");                   \
    } while (0)

    LOADC3(0, 0);
    LOADC3(1, 32);

    int stage = 0;
    for (int i = 0; i < KT; i++) {
        if (i < KT - 1)
            asm volatile("cp.async.wait_group 1;" ::: "memory");
        else
            asm volatile("cp.async.wait_group 0;" ::: "memory");
        __syncthreads();
        if (i + 2 < KT) {
            int ns = stage + 2;
            if (ns >= 3) ns -= 3;
            LOADC3(ns, (size_t)(i + 2) * 32);
        }
        const uint32_t sA = sb + (uint32_t)stage * STG3;
        const uint32_t sB = sA + 16384;
#pragma unroll
        for (int ks = 0; ks < 4; ks++) {
            const uint32_t va = ((2u * ks + asel) ^ swz) << 4;
            const uint32_t vb = ((2u * ks + bsel) ^ swz) << 4;
            uint32_t af[4][4];
#pragma unroll
            for (int ii = 0; ii < 4; ii++)
                LDSM4(af[ii], sA + a_ro + ii * 2048 + va);
            uint32_t bf[8][2];
#pragma unroll
            for (int nb = 0; nb < 4; nb++) {
                uint32_t r[4];
                LDSM4(r, sB + b_ro + nb * 2048 + vb);
                bf[2 * nb][0] = r[0]; bf[2 * nb][1] = r[1];
                bf[2 * nb + 1][0] = r[2]; bf[2 * nb + 1][1] = r[3];
            }
#pragma unroll
            for (int ii = 0; ii < 4; ii++)
#pragma unroll
                for (int j = 0; j < 8; j++) MMA_TF32(acc[ii][j], af[ii], bf[j]);
        }
        stage++;
        if (stage == 3) stage = 0;
    }

#pragma unroll
    for (int i = 0; i < 4; i++) {
        int r0 = m0 + wm + i * 16 + (lane >> 2);
#pragma unroll
        for (int j = 0; j < 8; j++) {
            int c0 = n0 + wn + j * 8 + (lane & 3) * 2;
            float v0 = acc[i][j][0], v1 = acc[i][j][1];
            float v2 = acc[i][j][2], v3 = acc[i][j][3];
            if (bias) {
                float b0 = bias[c0], b1 = bias[c0 + 1];
                v0 += b0; v1 += b1; v2 += b0; v3 += b1;
            }
            if (relu) {
                v0 = fmaxf(v0, 0.f); v1 = fmaxf(v1, 0.f);
                v2 = fmaxf(v2, 0.f); v3 = fmaxf(v3, 0.f);
            }
            size_t o0 = (size_t)r0 * N + c0;
            size_t o1 = (size_t)(r0 + 8) * N + c0;
            if (res) {
                v0 += res[o0]; v1 += res[o0 + 1];
                v2 += res[o1]; v3 += res[o1 + 1];
            }
            if (rnd) {
                v0 = rtf32(v0); v1 = rtf32(v1);
                v2 = rtf32(v2); v3 = rtf32(v3);
            }
            C[o0] = v0; C[o0 + 1] = v1;
            C[o1] = v2; C[o1 + 1] = v3;
        }
    }
#undef LOADC3
}

// ---------------------------------------------------------------------------
// sq_gemm: attention S = Q K^T, K=64 specialized single-shot (no pipeline).
// 128x128 tile, 256 threads, causal skip, 64 KB smem, 2 CTA/SM.
// Both 32-wide k-chunks loaded upfront; one sync; same MMA order as hgemm
// (chunk0 ks0..3 then chunk1 ks0..3) => bit-identical accumulation.
// ---------------------------------------------------------------------------
#define SQ_STG 32768
#define SQ_SMEM (2 * SQ_STG)

__global__ __launch_bounds__(256, 2) void sq_gemm(
    const float* __restrict__ qkv, float* __restrict__ S) {
    extern __shared__ __align__(1024) char smem[];
    const int m0 = blockIdx.y * 128, n0 = blockIdx.x * 128;
    if (n0 > m0 + 127) return;
    const int z = blockIdx.z, b = z >> 4, h = z & 15;
    const float* A = qkv + (size_t)b * TT * QKVN + h * 64;           // Q
    const float* Bt = qkv + (size_t)b * TT * QKVN + 1024 + h * 64;   // K
    float* C = S + (size_t)z * (TT * TT);

    const uint32_t sb = smem_u32(smem);
    const int tid = threadIdx.x, lane = tid & 31, wid = tid >> 5;
    const int wm = (wid >> 1) * 32, wn = (wid & 1) * 64;

    const int lrow = tid >> 3, lu = tid & 7;
    const float* srcA = A + (size_t)(m0 + lrow) * QKVN + lu * 4;
    const float* srcB = Bt + (size_t)(n0 + lrow) * QKVN + lu * 4;
    const size_t rstep = (size_t)32 * QKVN;
    const uint32_t d0 = (uint32_t)lrow * 128 + (((uint32_t)(lu ^ (lrow & 7))) << 4);

    const uint32_t asel = lane >> 4;
    const uint32_t bsel = (lane >> 3) & 1;
    const uint32_t swz = lane & 7;
    const uint32_t a_ro = (uint32_t)(wm + (lane & 7) + ((lane >> 3) & 1) * 8) * 128;
    const uint32_t b_ro = (uint32_t)(wn + (lane & 7) + (lane >> 4) * 8) * 128;

    // load both k-chunks (cols 0..31 and 32..63) into the two buffers
#pragma unroll
    for (int st = 0; st < 2; st++) {
        uint32_t bA = sb + (uint32_t)st * SQ_STG;
        uint32_t bB = bA + 16384;
        const float* pa = srcA + st * 32;
        const float* pb = srcB + st * 32;
#pragma unroll
        for (int ii = 0; ii < 4; ii++) cp16(bA + d0 + ii * 4096, pa + ii * rstep);
#pragma unroll
        for (int ii = 0; ii < 4; ii++) cp16(bB + d0 + ii * 4096, pb + ii * rstep);
    }
    asm volatile("cp.async.commit_group;" ::: "memory");
    asm volatile("cp.async.wait_group 0;" ::: "memory");
    __syncthreads();

    float acc[2][8][4];
#pragma unroll
    for (int i = 0; i < 2; i++)
#pragma unroll
        for (int j = 0; j < 8; j++)
#pragma unroll
            for (int c = 0; c < 4; c++) acc[i][j][c] = 0.f;

#pragma unroll
    for (int st = 0; st < 2; st++) {
        const uint32_t sA = sb + (uint32_t)st * SQ_STG;
        const uint32_t sB = sA + 16384;
#pragma unroll
        for (int ks = 0; ks < 4; ks++) {
            const uint32_t va = ((2u * ks + asel) ^ swz) << 4;
            const uint32_t vb = ((2u * ks + bsel) ^ swz) << 4;
            uint32_t af[2][4];
            LDSM4(af[0], sA + a_ro + va);
            LDSM4(af[1], sA + a_ro + 2048 + va);
            uint32_t bf[8][2];
#pragma unroll
            for (int nb = 0; nb < 4; nb++) {
                uint32_t r[4];
                LDSM4(r, sB + b_ro + nb * 2048 + vb);
                bf[2 * nb][0] = r[0]; bf[2 * nb][1] = r[1];
                bf[2 * nb + 1][0] = r[2]; bf[2 * nb + 1][1] = r[3];
            }
#pragma unroll
            for (int ii = 0; ii < 2; ii++)
#pragma unroll
                for (int j = 0; j < 8; j++) MMA_TF32(acc[ii][j], af[ii], bf[j]);
        }
    }

#pragma unroll
    for (int i = 0; i < 2; i++) {
        int r0 = m0 + wm + i * 16 + (lane >> 2);
#pragma unroll
        for (int j = 0; j < 8; j++) {
            int c0 = n0 + wn + j * 8 + (lane & 3) * 2;
            size_t o0 = (size_t)r0 * TT + c0;
            size_t o1 = (size_t)(r0 + 8) * TT + c0;
            C[o0] = acc[i][j][0]; C[o0 + 1] = acc[i][j][1];
            C[o1] = acc[i][j][2]; C[o1 + 1] = acc[i][j][3];
        }
    }
}

// ---------------------------------------------------------------------------
// Softmax over S rows: warp per row, 3 streaming passes (max, sum, write).
// Writes tf32 P in place, zero-fill up to row's 128-aligned width.
// ---------------------------------------------------------------------------
__global__ __launch_bounds__(256) void softmax_kernel() {
    int gid = blockIdx.x * 8 + (threadIdx.x >> 5);
    int lane = threadIdx.x & 31;
    int z = gid >> 10, i = gid & 1023;
    float* sr = g_s + (size_t)z * (TT * TT) + (size_t)i * TT;
    int L = i + 1;
    int W = ((i >> 7) + 1) << 7;
    float m = -1e30f;
    for (int j0 = lane * 4; j0 < W; j0 += 128) {
        float4 v = *(const float4*)(sr + j0);
        if (j0 + 0 < L) m = fmaxf(m, v.x);
        if (j0 + 1 < L) m = fmaxf(m, v.y);
        if (j0 + 2 < L) m = fmaxf(m, v.z);
        if (j0 + 3 < L) m = fmaxf(m, v.w);
    }
    m = warpMax(m) * 0.125f;
    float sum = 0.f;
    for (int j0 = lane * 4; j0 < W; j0 += 128) {
        float4 v = *(const float4*)(sr + j0);
        if (j0 + 0 < L) sum += __expf(v.x * 0.125f - m);
        if (j0 + 1 < L) sum += __expf(v.y * 0.125f - m);
        if (j0 + 2 < L) sum += __expf(v.z * 0.125f - m);
        if (j0 + 3 < L) sum += __expf(v.w * 0.125f - m);
    }
    float inv = 1.f / warpSum(sum);
    for (int j0 = lane * 4; j0 < W; j0 += 128) {
        float4 v = *(const float4*)(sr + j0);
        float4 p;
        p.x = (j0 + 0 < L) ? rtf32(__expf(v.x * 0.125f - m) * inv) : 0.f;
        p.y = (j0 + 1 < L) ? rtf32(__expf(v.y * 0.125f - m) * inv) : 0.f;
        p.z = (j0 + 2 < L) ? rtf32(__expf(v.z * 0.125f - m) * inv) : 0.f;
        p.w = (j0 + 3 < L) ? rtf32(__expf(v.w * 0.125f - m) * inv) : 0.f;
        *(float4*)(sr + j0) = p;
    }
}

// ---------------------------------------------------------------------------
// PV gemm: O[128m x 64n] = P[m,k] * Vt[n,k]^T per (z, m-block), causal
// K truncation. 128 threads, 3-stage cp.async.
// ---------------------------------------------------------------------------
#define PV_STG 24576
#define PV_SMEM (3 * PV_STG)

__global__ __launch_bounds__(128, 2) void pv_gemm() {
    extern __shared__ __align__(1024) char smem[];
    const uint32_t sb = smem_u32(smem);
    const int tid = threadIdx.x, lane = tid & 31, wid = tid >> 5;
    const int mb = blockIdx.x, z = blockIdx.y;
    const int m0 = mb * 128;
    const int KT = (mb + 1) * 4;

    const float* P = g_s + (size_t)z * (TT * TT);
    const float* Vt = g_vt + (size_t)z * (HS * TT);

    const int lrow = tid >> 3, lu = tid & 7;
    const float* srcA = P + (size_t)(m0 + lrow) * TT + lu * 4;
    const float* srcB = Vt + (size_t)lrow * TT + lu * 4;
    const uint32_t d0 = (uint32_t)lrow * 128 + (((uint32_t)(lu ^ (lrow & 7))) << 4);

    const uint32_t asel = lane >> 4;
    const uint32_t bsel = (lane >> 3) & 1;
    const uint32_t swz = lane & 7;
    const int wm = wid * 32;
    const uint32_t a_ro = (uint32_t)(wm + (lane & 7) + ((lane >> 3) & 1) * 8) * 128;
    const uint32_t b_ro = (uint32_t)((lane & 7) + (lane >> 4) * 8) * 128;

    float acc[2][8][4];
#pragma unroll
    for (int i = 0; i < 2; i++)
#pragma unroll
        for (int j = 0; j < 8; j++)
#pragma unroll
            for (int c = 0; c < 4; c++) acc[i][j][c] = 0.f;

#define PLOADC(s, kof)                                                         \
    do {                                                                       \
        uint32_t bA = sb + (uint32_t)(s) * PV_STG;                             \
        uint32_t bB = bA + 16384;                                              \
        const float* pa = srcA + (kof);                                        \
        const float* pb = srcB + (kof);                                        \
        _Pragma("unroll") for (int ii = 0; ii < 8; ii++)                       \
            cp16(bA + d0 + ii * 2048, pa + (size_t)ii * 16 * TT);              \
        _Pragma("unroll") for (int ii = 0; ii < 4; ii++)                       \
            cp16(bB + d0 + ii * 2048, pb + (size_t)ii * 16 * TT);              \
        asm volatile("cp.async.commit_group;" ::: "memory");                   \
    } while (0)

    PLOADC(0, 0);
    PLOADC(1, 32);

    int stage = 0;
    for (int i = 0; i < KT; i++) {
        if (i < KT - 1)
            asm volatile("cp.async.wait_group 1;" ::: "memory");
        else
            asm volatile("cp.async.wait_group 0;" ::: "memory");
        __syncthreads();
        if (i + 2 < KT) {
            int ns = stage + 2;
            if (ns >= 3) ns -= 3;
            PLOADC(ns, (size_t)(i + 2) * 32);
        }
        const uint32_t sA = sb + (uint32_t)stage * PV_STG;
        const uint32_t sB = sA + 16384;
#pragma unroll
        for (int ks = 0; ks < 4; ks++) {
            const uint32_t va = ((2u * ks + asel) ^ swz) << 4;
            const uint32_t vb = ((2u * ks + bsel) ^ swz) << 4;
            uint32_t af[2][4];
            LDSM4(af[0], sA + a_ro + va);
            LDSM4(af[1], sA + a_ro + 2048 + va);
            uint32_t bf[8][2];
#pragma unroll
            for (int nb = 0; nb < 4; nb++) {
                uint32_t r[4];
                LDSM4(r, sB + b_ro + nb * 2048 + vb);
                bf[2 * nb][0] = r[0]; bf[2 * nb][1] = r[1];
                bf[2 * nb + 1][0] = r[2]; bf[2 * nb + 1][1] = r[3];
            }
#pragma unroll
            for (int ii = 0; ii < 2; ii++)
#pragma unroll
                for (int j = 0; j < 8; j++) MMA_TF32(acc[ii][j], af[ii], bf[j]);
        }
        stage++;
        if (stage == 3) stage = 0;
    }

    const int b = z >> 4, h = z & 15;
#pragma unroll
    for (int i = 0; i < 2; i++) {
        int r0 = m0 + wm + i * 16 + (lane >> 2);
        int tok0 = b * TT + r0;
#pragma unroll
        for (int j = 0; j < 8; j++) {
            int c0 = h * 64 + j * 8 + (lane & 3) * 2;
            size_t o0 = (size_t)tok0 * DM + c0;
            size_t o1 = (size_t)(tok0 + 8) * DM + c0;
            g_ao[o0] = rtf32(acc[i][j][0]);
            g_ao[o0 + 1] = rtf32(acc[i][j][1]);
            g_ao[o1] = rtf32(acc[i][j][2]);
            g_ao[o1 + 1] = rtf32(acc[i][j][3]);
        }
    }
#undef PLOADC
}

// ---------------------------------------------------------------------------
// Loss: single-pass online softmax per row (float4 reads), deterministic mean
// ---------------------------------------------------------------------------
__global__ __launch_bounds__(256) void loss_row_kernel(const float* __restrict__ logits,
                                                       const int* __restrict__ targets) {
    int row = blockIdx.x, tid = threadIdx.x;
    const float4* lr4 = (const float4*)(logits + (size_t)row * VV);
    float m = -1e30f, s = 0.f;
    for (int c = tid; c < VV / 4; c += 256) {
        float4 v = lr4[c];
        float vm = fmaxf(fmaxf(v.x, v.y), fmaxf(v.z, v.w));
        float nm = fmaxf(m, vm);
        s = s * __expf(m - nm) + __expf(v.x - nm) + __expf(v.y - nm) +
            __expf(v.z - nm) + __expf(v.w - nm);
        m = nm;
    }
    float M = blockReduceMax(m);
    s *= __expf(m - M);
    float S = blockReduceSum(s);
    if (tid == 0)
        g_rowloss[row] = (M + logf(S)) - logits[(size_t)row * VV + targets[row]];
}

__global__ __launch_bounds__(256) void loss_final_kernel(float* __restrict__ out) {
    float s = 0.f;
    for (int i = threadIdx.x; i < NP; i += 256) s += g_rowloss[i];
    s = blockReduceSum(s);
    if (threadIdx.x == 0) out[0] = s * (1.f / NP);
}

// ---------------------------------------------------------------------------
// Host launcher
// ---------------------------------------------------------------------------
extern "C" void kernel_launch(void* const* d_in, const int* in_sizes, int n_in,
                              void* d_out, int out_size) {
    const int*   idx  = (const int*)d_in[0];
    const int*   ibx  = (const int*)d_in[1];
    const int*   tgt  = (const int*)d_in[2];
    const float* tok  = (const float*)d_in[3];
    const float* pos  = (const float*)d_in[4];
    const float* book = (const float*)d_in[5];
    const float* Wq   = (const float*)d_in[6];
    const float* Wk   = (const float*)d_in[7];
    const float* Wv   = (const float*)d_in[8];
    const float* Wo   = (const float*)d_in[9];
    const float* bo   = (const float*)d_in[10];
    const float* ln1s = (const float*)d_in[11];
    const float* ln1b = (const float*)d_in[12];
    const float* ln2s = (const float*)d_in[13];
    const float* ln2b = (const float*)d_in[14];
    const float* W1   = (const float*)d_in[15];
    const float* b1   = (const float*)d_in[16];
    const float* W2   = (const float*)d_in[17];
    const float* b2   = (const float*)d_in[18];
    const float* lnfs = (const float*)d_in[19];
    const float* lnfb = (const float*)d_in[20];
    const float* Wh   = (const float*)d_in[21];
    const float* bh   = (const float*)d_in[22];
    float* out = (float*)d_out;

    float *x, *qkv, *s_, *wt, *h, *ao, *h2, *ff;
    cudaGetSymbolAddress((void**)&x,   g_x);
    cudaGetSymbolAddress((void**)&qkv, g_qkv);
    cudaGetSymbolAddress((void**)&s_,  g_s);
    cudaGetSymbolAddress((void**)&wt,  g_wt);
    cudaGetSymbolAddress((void**)&h,   g_h);
    cudaGetSymbolAddress((void**)&ao,  g_ao);
    cudaGetSymbolAddress((void**)&h2,  g_h2);
    cudaGetSymbolAddress((void**)&ff,  g_ff);

    cudaFuncSetAttribute(sq_gemm, cudaFuncAttributeMaxDynamicSharedMemorySize,
                         SQ_SMEM);
    cudaFuncSetAttribute(hgemm3, cudaFuncAttributeMaxDynamicSharedMemorySize,
                         GEMM3_SMEM);
    cudaFuncSetAttribute(pv_gemm, cudaFuncAttributeMaxDynamicSharedMemorySize,
                         PV_SMEM);

    wtr_all_kernel<<<TIL_TOTAL, 256>>>(Wq, Wk, Wv, Wo, W1, W2, Wh, wt);
    embed_kernel<<<NP * DM / 1024, 256>>>(idx, tok, pos);
    book_kernel<<<NP * DBK / 256, 256>>>(ibx, book);

    for (int l = 0; l < LL; l++) {
        ln_kernel<<<NP / 4, 128>>>(x, ln1s + l * DM, ln1b + l * DM, h, DM);
        hgemm3<<<dim3(QKVN / 128, NP / 128), 128, GEMM3_SMEM>>>(
            h, DM, wt + OFF_QKV + (size_t)l * 3 * DM * DM, DM,
            nullptr, nullptr, qkv, NP, QKVN, DM, 0, 1);
        vt_kernel<<<dim3(TT / 64, ZZ), 256>>>();
        sq_gemm<<<dim3(TT / 128, TT / 128, ZZ), 256, SQ_SMEM>>>(qkv, s_);
        softmax_kernel<<<ZZ * TT / 8, 256>>>();
        pv_gemm<<<dim3(TT / 128, ZZ), 128, PV_SMEM>>>();
        hgemm3<<<dim3(DM / 128, NP / 128), 128, GEMM3_SMEM>>>(
            ao, DM, wt + OFF_WO + (size_t)l * DM * DM, DM,
            bo + l * DM, x, x, NP, DM, DM, 0, 0);
        ln_kernel<<<NP / 4, 128>>>(x, ln2s + l * DM, ln2b + l * DM, h2, DIN);
        hgemm3<<<dim3(DFF / 128, NP / 128), 128, GEMM3_SMEM>>>(
            h2, DIN, wt + OFF_W1 + (size_t)l * DFF * DIN, DIN,
            b1 + l * DFF, nullptr, ff, NP, DFF, DIN, 1, 1);
        hgemm3<<<dim3(DM / 128, NP / 128), 128, GEMM3_SMEM>>>(
            ff, DFF, wt + OFF_W2 + (size_t)l * DM * DFF, DFF,
            b2 + l * DM, x, x, NP, DM, DFF, 0, 0);
    }

    ln_kernel<<<NP / 4, 128>>>(x, lnfs, lnfb, h, DM);
    hgemm3<<<dim3(VV / 128, NP / 128), 128, GEMM3_SMEM>>>(
        h, DM, wt + OFF_WH, DM, bh, nullptr, out, NP, VV, DM, 0, 0);
    loss_row_kernel<<<NP, 256>>>(out, tgt);
    if (out_size > NP * VV)
        loss_final_kernel<<<1, 256>>>(out + (size_t)NP * VV);
}